// round 4
// baseline (speedup 1.0000x reference)
#include <cuda_runtime.h>
#include <math.h>

#define NN   8192
#define DIN  128
#define DH   48
#define DH1  256
#define DH2  128
#define DOUT 32

// ------------------------- scratch (device globals; no allocs) -------------
__device__ float g_Wh[NN * DH];
__device__ float g_s[NN];
__device__ float g_ea[NN];   // exp(s)
__device__ float g_eb[NN];   // exp(0.2 s)
__device__ float g_hp[NN * DH];
__device__ float g_hn[NN * DH];
__device__ float g_m1[NN * DH1];
__device__ float g_m2[NN * DH2];

// ------------------------- f32x2 helpers -----------------------------------
__device__ __forceinline__ unsigned long long dup2(float w) {
    unsigned long long r;
    unsigned int wi = __float_as_uint(w);
    asm("mov.b64 %0, {%1, %1};" : "=l"(r) : "r"(wi));
    return r;
}
__device__ __forceinline__ void ffma2(unsigned long long& c,
                                      unsigned long long a,
                                      unsigned long long b) {
    asm("fma.rn.f32x2 %0, %1, %2, %0;" : "+l"(c) : "l"(a), "l"(b));
}

// ------------------------- generic tiled GEMM ------------------------------
// C[M x Nn] = act(A[M x K] @ W[Nn x K]^T + bias)
// requires: M % 64 == 0, K % 16 == 0. Nn arbitrary (guarded).
__global__ void __launch_bounds__(256) gemm_kernel(
    const float* __restrict__ A, const float* __restrict__ W,
    const float* __restrict__ bias, float* __restrict__ C,
    int M, int Nn, int K, int relu)
{
    __shared__ __align__(16) float As[16][68];   // [k][m], pad 68 -> 272B rows (16B aligned)
    __shared__ __align__(16) float Ws[16][68];   // [k][n]

    int tid = threadIdx.x;
    int tx = tid & 15, ty = tid >> 4;
    int m0 = blockIdx.y * 64, n0 = blockIdx.x * 64;

    float acc[4][4];
#pragma unroll
    for (int r = 0; r < 4; r++)
#pragma unroll
        for (int c = 0; c < 4; c++) acc[r][c] = 0.f;

    int lr = tid >> 2;          // 0..63
    int lc = (tid & 3) * 4;     // 0,4,8,12
    const float* Ap = A + (size_t)(m0 + lr) * K + lc;
    bool wvalid = (n0 + lr) < Nn;
    const float* Wp = W + (size_t)(n0 + lr) * K + lc;

    for (int k0 = 0; k0 < K; k0 += 16) {
        float4 av = *(const float4*)(Ap + k0);
        float4 wv = wvalid ? *(const float4*)(Wp + k0) : make_float4(0.f, 0.f, 0.f, 0.f);
        __syncthreads();
        As[lc + 0][lr] = av.x; As[lc + 1][lr] = av.y;
        As[lc + 2][lr] = av.z; As[lc + 3][lr] = av.w;
        Ws[lc + 0][lr] = wv.x; Ws[lc + 1][lr] = wv.y;
        Ws[lc + 2][lr] = wv.z; Ws[lc + 3][lr] = wv.w;
        __syncthreads();
#pragma unroll
        for (int kk = 0; kk < 16; kk++) {
            float4 a4 = *(const float4*)&As[kk][ty * 4];
            float4 b4 = *(const float4*)&Ws[kk][tx * 4];
            acc[0][0] = fmaf(a4.x, b4.x, acc[0][0]);
            acc[0][1] = fmaf(a4.x, b4.y, acc[0][1]);
            acc[0][2] = fmaf(a4.x, b4.z, acc[0][2]);
            acc[0][3] = fmaf(a4.x, b4.w, acc[0][3]);
            acc[1][0] = fmaf(a4.y, b4.x, acc[1][0]);
            acc[1][1] = fmaf(a4.y, b4.y, acc[1][1]);
            acc[1][2] = fmaf(a4.y, b4.z, acc[1][2]);
            acc[1][3] = fmaf(a4.y, b4.w, acc[1][3]);
            acc[2][0] = fmaf(a4.z, b4.x, acc[2][0]);
            acc[2][1] = fmaf(a4.z, b4.y, acc[2][1]);
            acc[2][2] = fmaf(a4.z, b4.z, acc[2][2]);
            acc[2][3] = fmaf(a4.z, b4.w, acc[2][3]);
            acc[3][0] = fmaf(a4.w, b4.x, acc[3][0]);
            acc[3][1] = fmaf(a4.w, b4.y, acc[3][1]);
            acc[3][2] = fmaf(a4.w, b4.z, acc[3][2]);
            acc[3][3] = fmaf(a4.w, b4.w, acc[3][3]);
        }
    }
#pragma unroll
    for (int r = 0; r < 4; r++) {
        int m = m0 + ty * 4 + r;
#pragma unroll
        for (int c = 0; c < 4; c++) {
            int n = n0 + tx * 4 + c;
            if (n < Nn) {
                float v = acc[r][c] + (bias ? bias[n] : 0.f);
                if (relu) v = fmaxf(v, 0.f);
                C[(size_t)m * Nn + n] = v;
            }
        }
    }
}

// ------------------------- s, exp(s), exp(0.2 s) ---------------------------
__global__ void __launch_bounds__(256) sab_kernel(const float* __restrict__ avec)
{
    int i = blockIdx.x * blockDim.x + threadIdx.x;
    const float4* w = (const float4*)(g_Wh + (size_t)i * DH);
    float acc = 0.f;
#pragma unroll
    for (int q = 0; q < DH / 4; q++) {
        float4 wv = w[q];
        float4 av = ((const float4*)avec)[q];
        acc += wv.x * av.x;
        acc += wv.y * av.y;
        acc += wv.z * av.z;
        acc += wv.w * av.w;
    }
    g_s[i]  = acc;
    g_ea[i] = expf(acc);
    g_eb[i] = expf(0.2f * acc);
}

// ------------------------- attention ---------------------------------------
// hp[i,:] = (sum_j w_ij * Wh[j,:]) / (sum_j w_ij)
// w_ij = adj_ij ? ( (s_i+s_j > 0) ? e^{s_i} e^{s_j} : e^{0.2 s_i} e^{0.2 s_j} ) : 0
__device__ __forceinline__ float wfun(int a, float sj, float eaj, float ebj,
                                      float si, float eai, float ebi)
{
    float t = si + sj;
    float w = (t > 0.f) ? (eai * eaj) : (ebi * ebj);
    return a ? w : 0.f;
}

#define TIA 64
#define TJA 64

__global__ void __launch_bounds__(128, 1) attn_kernel(const int* __restrict__ adj)
{
    __shared__ __align__(16) float Wt[TJA * TIA];    // weights [j][i]
    __shared__ __align__(16) float Whs[TJA * DH];    // Wh rows for tile
    __shared__ float Zs[TIA];

    int tid = threadIdx.x;
    int I0 = blockIdx.x * TIA;

    // phase-A coords: fixed row i per thread, half the j-groups each
    int irel = tid & 63;
    int ghalf = tid >> 6;
    int i = I0 + irel;
    float si = g_s[i], eai = g_ea[i], ebi = g_eb[i];
    const int* adjrow = adj + (size_t)i * NN;

    // phase-B coords: 4 rows x 6 dims per thread
    int tx = tid & 7;        // dim group
    int ty = tid >> 3;       // row group (0..15)
    int d0 = tx * 6;

    unsigned long long acc[4][3];
#pragma unroll
    for (int r = 0; r < 4; r++)
#pragma unroll
        for (int q = 0; q < 3; q++) acc[r][q] = 0ull;
    float Zacc = 0.f;

    for (int J0 = 0; J0 < NN; J0 += TJA) {
        __syncthreads();   // previous tile fully consumed

        // --- stage Wh rows for this j-tile (64 x 48 floats = 768 float4) ---
        const float4* src = (const float4*)(g_Wh + (size_t)J0 * DH);
#pragma unroll
        for (int t = 0; t < 6; t++) {
            int idx = t * 128 + tid;
            ((float4*)Whs)[idx] = src[idx];
        }

        // --- build weight tile Wt[j][i] ---
#pragma unroll
        for (int it = 0; it < 8; it++) {
            int g = ghalf + it * 2;     // 0..15
            int j0 = g * 4;
            int4   a4  = *(const int4*)(adjrow + J0 + j0);
            float4 sj  = *(const float4*)(g_s  + J0 + j0);
            float4 eaj = *(const float4*)(g_ea + J0 + j0);
            float4 ebj = *(const float4*)(g_eb + J0 + j0);
            Wt[(j0 + 0) * TIA + irel] = wfun(a4.x, sj.x, eaj.x, ebj.x, si, eai, ebi);
            Wt[(j0 + 1) * TIA + irel] = wfun(a4.y, sj.y, eaj.y, ebj.y, si, eai, ebi);
            Wt[(j0 + 2) * TIA + irel] = wfun(a4.z, sj.z, eaj.z, ebj.z, si, eai, ebi);
            Wt[(j0 + 3) * TIA + irel] = wfun(a4.w, sj.w, eaj.w, ebj.w, si, eai, ebi);
        }
        __syncthreads();

        // --- accumulate: acc[r][:] += w[j][row] * Wh[j][dims] (f32x2 FMA) ---
#pragma unroll 8
        for (int j = 0; j < TJA; j++) {
            float4 w4 = *(const float4*)&Wt[j * TIA + ty * 4];
            const float* up = &Whs[j * DH + d0];
            unsigned long long u0 = *(const unsigned long long*)(up);
            unsigned long long u1 = *(const unsigned long long*)(up + 2);
            unsigned long long u2 = *(const unsigned long long*)(up + 4);
            unsigned long long wp;
            wp = dup2(w4.x); ffma2(acc[0][0], wp, u0); ffma2(acc[0][1], wp, u1); ffma2(acc[0][2], wp, u2);
            wp = dup2(w4.y); ffma2(acc[1][0], wp, u0); ffma2(acc[1][1], wp, u1); ffma2(acc[1][2], wp, u2);
            wp = dup2(w4.z); ffma2(acc[2][0], wp, u0); ffma2(acc[2][1], wp, u1); ffma2(acc[2][2], wp, u2);
            wp = dup2(w4.w); ffma2(acc[3][0], wp, u0); ffma2(acc[3][1], wp, u1); ffma2(acc[3][2], wp, u2);
        }

        // --- Z partial sums (rows owned by tid<64; pure reads of Wt) ---
        if (tid < TIA) {
            float z0 = 0.f, z1 = 0.f, z2 = 0.f, z3 = 0.f;
#pragma unroll
            for (int j = 0; j < TJA; j += 4) {
                z0 += Wt[(j + 0) * TIA + tid];
                z1 += Wt[(j + 1) * TIA + tid];
                z2 += Wt[(j + 2) * TIA + tid];
                z3 += Wt[(j + 3) * TIA + tid];
            }
            Zacc += (z0 + z1) + (z2 + z3);
        }
    }

    if (tid < TIA) Zs[tid] = Zacc;
    __syncthreads();

#pragma unroll
    for (int r = 0; r < 4; r++) {
        int row = ty * 4 + r;
        float rz = 1.0f / Zs[row];
        float* op = g_hp + (size_t)(I0 + row) * DH + d0;
#pragma unroll
        for (int q = 0; q < 3; q++) {
            float2 v = *reinterpret_cast<float2*>(&acc[r][q]);
            v.x *= rz; v.y *= rz;
            *(float2*)(op + 2 * q) = v;
        }
    }
}

// ------------------------- LayerNorm ---------------------------------------
__global__ void __launch_bounds__(256) ln_kernel(const float* __restrict__ gamma,
                                                 const float* __restrict__ beta)
{
    int i = blockIdx.x * blockDim.x + threadIdx.x;
    float v[DH];
    const float4* p = (const float4*)(g_hp + (size_t)i * DH);
#pragma unroll
    for (int q = 0; q < DH / 4; q++) {
        float4 t = p[q];
        v[q * 4 + 0] = t.x; v[q * 4 + 1] = t.y;
        v[q * 4 + 2] = t.z; v[q * 4 + 3] = t.w;
    }
    float s = 0.f;
#pragma unroll
    for (int k = 0; k < DH; k++) s += v[k];
    float mu = s * (1.0f / DH);
    float vs = 0.f;
#pragma unroll
    for (int k = 0; k < DH; k++) {
        float d = v[k] - mu;
        vs += d * d;
    }
    float rstd = rsqrtf(vs * (1.0f / DH) + 1e-5f);
    float* o = g_hn + (size_t)i * DH;
#pragma unroll
    for (int k = 0; k < DH; k++)
        o[k] = (v[k] - mu) * rstd * gamma[k] + beta[k];
}

// ------------------------- launch ------------------------------------------
extern "C" void kernel_launch(void* const* d_in, const int* in_sizes, int n_in,
                              void* d_out, int out_size)
{
    const float* x     = (const float*)d_in[0];
    const int*   adj   = (const int*)  d_in[1];
    const float* Wg    = (const float*)d_in[2];
    const float* avec  = (const float*)d_in[3];
    const float* gamma = (const float*)d_in[4];
    const float* beta  = (const float*)d_in[5];
    const float* W1    = (const float*)d_in[6];
    const float* b1    = (const float*)d_in[7];
    const float* W2    = (const float*)d_in[8];
    const float* b2    = (const float*)d_in[9];
    const float* W3    = (const float*)d_in[10];
    const float* b3    = (const float*)d_in[11];
    float* out = (float*)d_out;

    float *Wh, *hn, *m1, *m2;
    cudaGetSymbolAddress((void**)&Wh, g_Wh);
    cudaGetSymbolAddress((void**)&hn, g_hn);
    cudaGetSymbolAddress((void**)&m1, g_m1);
    cudaGetSymbolAddress((void**)&m2, g_m2);

    // Wh = x @ W_gat^T            [8192 x 48]
    gemm_kernel<<<dim3(1, NN / 64), 256>>>(x, Wg, nullptr, Wh, NN, DH, DIN, 0);
    // s, exp(s), exp(0.2 s)
    sab_kernel<<<NN / 256, 256>>>(avec);
    // attention -> g_hp
    attn_kernel<<<NN / TIA, 128>>>(adj);
    // layernorm -> g_hn
    ln_kernel<<<NN / 256, 256>>>(gamma, beta);
    // MLP head
    gemm_kernel<<<dim3(DH1 / 64, NN / 64), 256>>>(hn, W1, b1, m1, NN, DH1, DH, 1);
    gemm_kernel<<<dim3(DH2 / 64, NN / 64), 256>>>(m1, W2, b2, m2, NN, DH2, DH1, 1);
    gemm_kernel<<<dim3(1, NN / 64), 256>>>(m2, W3, b3, out, NN, DOUT, DH2, 0);
}

// round 5
// speedup vs baseline: 1.2466x; 1.2466x over previous
#include <cuda_runtime.h>
#include <math.h>

#define NN   8192
#define DIN  128
#define DH   48
#define DH1  256
#define DH2  128
#define DOUT 32

typedef unsigned long long ull;

// ------------------------- scratch (device globals; no allocs) -------------
__device__ float g_Wh[NN * DH];
__device__ float g_s[NN];
__device__ float g_ea[NN];   // exp(s)
__device__ float g_eb[NN];   // exp(0.2 s)
__device__ float g_hn[NN * DH];
__device__ float g_m1[NN * DH1];
__device__ float g_m2[NN * DH2];

// ------------------------- helpers -----------------------------------------
__device__ __forceinline__ void ffma2(ull& c, ull a, ull b) {
    asm("fma.rn.f32x2 %0, %1, %2, %0;" : "+l"(c) : "l"(a), "l"(b));
}
__device__ __forceinline__ void cpa16(void* dst_smem, const void* src) {
    unsigned int d = (unsigned int)__cvta_generic_to_shared(dst_smem);
    asm volatile("cp.async.cg.shared.global [%0], [%1], 16;" :: "r"(d), "l"(src));
}
__device__ __forceinline__ void cpa_commit() {
    asm volatile("cp.async.commit_group;" ::: "memory");
}
__device__ __forceinline__ void cpa_wait0() {
    asm volatile("cp.async.wait_group 0;" ::: "memory");
}

// ------------------------- generic tiled GEMM ------------------------------
// C[M x Nn] = act(A[M x K] @ W[Nn x K]^T + bias); M%64==0, K%16==0.
__global__ void __launch_bounds__(256) gemm_kernel(
    const float* __restrict__ A, const float* __restrict__ W,
    const float* __restrict__ bias, float* __restrict__ C,
    int M, int Nn, int K, int relu)
{
    __shared__ __align__(16) float As[16][68];
    __shared__ __align__(16) float Ws[16][68];

    int tid = threadIdx.x;
    int tx = tid & 15, ty = tid >> 4;
    int m0 = blockIdx.y * 64, n0 = blockIdx.x * 64;

    float acc[4][4];
#pragma unroll
    for (int r = 0; r < 4; r++)
#pragma unroll
        for (int c = 0; c < 4; c++) acc[r][c] = 0.f;

    int lr = tid >> 2;
    int lc = (tid & 3) * 4;
    const float* Ap = A + (size_t)(m0 + lr) * K + lc;
    bool wvalid = (n0 + lr) < Nn;
    const float* Wp = W + (size_t)(n0 + lr) * K + lc;

    for (int k0 = 0; k0 < K; k0 += 16) {
        float4 av = *(const float4*)(Ap + k0);
        float4 wv = wvalid ? *(const float4*)(Wp + k0) : make_float4(0.f, 0.f, 0.f, 0.f);
        __syncthreads();
        As[lc + 0][lr] = av.x; As[lc + 1][lr] = av.y;
        As[lc + 2][lr] = av.z; As[lc + 3][lr] = av.w;
        Ws[lc + 0][lr] = wv.x; Ws[lc + 1][lr] = wv.y;
        Ws[lc + 2][lr] = wv.z; Ws[lc + 3][lr] = wv.w;
        __syncthreads();
#pragma unroll
        for (int kk = 0; kk < 16; kk++) {
            float4 a4 = *(const float4*)&As[kk][ty * 4];
            float4 b4 = *(const float4*)&Ws[kk][tx * 4];
            acc[0][0] = fmaf(a4.x, b4.x, acc[0][0]);
            acc[0][1] = fmaf(a4.x, b4.y, acc[0][1]);
            acc[0][2] = fmaf(a4.x, b4.z, acc[0][2]);
            acc[0][3] = fmaf(a4.x, b4.w, acc[0][3]);
            acc[1][0] = fmaf(a4.y, b4.x, acc[1][0]);
            acc[1][1] = fmaf(a4.y, b4.y, acc[1][1]);
            acc[1][2] = fmaf(a4.y, b4.z, acc[1][2]);
            acc[1][3] = fmaf(a4.y, b4.w, acc[1][3]);
            acc[2][0] = fmaf(a4.z, b4.x, acc[2][0]);
            acc[2][1] = fmaf(a4.z, b4.y, acc[2][1]);
            acc[2][2] = fmaf(a4.z, b4.z, acc[2][2]);
            acc[2][3] = fmaf(a4.z, b4.w, acc[2][3]);
            acc[3][0] = fmaf(a4.w, b4.x, acc[3][0]);
            acc[3][1] = fmaf(a4.w, b4.y, acc[3][1]);
            acc[3][2] = fmaf(a4.w, b4.z, acc[3][2]);
            acc[3][3] = fmaf(a4.w, b4.w, acc[3][3]);
        }
    }
#pragma unroll
    for (int r = 0; r < 4; r++) {
        int m = m0 + ty * 4 + r;
#pragma unroll
        for (int c = 0; c < 4; c++) {
            int n = n0 + tx * 4 + c;
            if (n < Nn) {
                float v = acc[r][c] + (bias ? bias[n] : 0.f);
                if (relu) v = fmaxf(v, 0.f);
                C[(size_t)m * Nn + n] = v;
            }
        }
    }
}

// ------------------------- s, exp(s), exp(0.2 s) ---------------------------
__global__ void __launch_bounds__(256) sab_kernel(const float* __restrict__ avec)
{
    int i = blockIdx.x * blockDim.x + threadIdx.x;
    const float4* w = (const float4*)(g_Wh + (size_t)i * DH);
    float acc = 0.f;
#pragma unroll
    for (int q = 0; q < DH / 4; q++) {
        float4 wv = w[q];
        float4 av = ((const float4*)avec)[q];
        acc += wv.x * av.x;
        acc += wv.y * av.y;
        acc += wv.z * av.z;
        acc += wv.w * av.w;
    }
    g_s[i]  = acc;
    g_ea[i] = expf(acc);
    g_eb[i] = expf(0.2f * acc);
}

// ------------------------- fused attention + LayerNorm ---------------------
// hn = LayerNorm( (sum_j w_ij * Wh[j,:]) / (sum_j w_ij) )
// w_ij = adj ? ((s_i+s_j>0) ? e^{s_i}e^{s_j} : e^{.2s_i}e^{.2s_j}) : 0
#define TIA 64
#define TJA 64
#define ADJP 68                      // padded adj row (ints) to dodge bank conflicts

// dynamic SMEM layout (float units)
#define SO_S    0                    // s table      [8192]
#define SO_EA   8192                 // ea table     [8192]
#define SO_EB   16384                // eb table     [8192]
#define SO_WT   24576                // Wt2 pairs    [64*64*2]
#define SO_WHS  32768                // Whs          [2][64*48]
#define SO_ADJ  38912                // adj tiles    [2][64*68] ints
#define SO_ZS   47616                // Z partials   [2][64]
#define SMEM_FLOATS (SO_ZS + 128)

__device__ __forceinline__ void issue_whs(float* dst, int J0, int tid) {
    const float* src = g_Wh + (size_t)J0 * DH;
#pragma unroll
    for (int p = 0; p < 6; p++) {
        int idx = tid + p * 128;             // 768 chunks of 16B
        cpa16(dst + idx * 4, src + idx * 4);
    }
}
__device__ __forceinline__ void issue_adj(int* dst, const int* __restrict__ adj,
                                          int I0, int J0, int tid) {
#pragma unroll
    for (int p = 0; p < 8; p++) {
        int idx = tid + p * 128;             // 1024 chunks: 64 rows x 16
        int rr = idx >> 4, c = idx & 15;
        cpa16(dst + rr * ADJP + c * 4,
              adj + (size_t)(I0 + rr) * NN + J0 + c * 4);
    }
}

__global__ void __launch_bounds__(128, 1) attn_kernel(
    const int* __restrict__ adj,
    const float* __restrict__ gamma, const float* __restrict__ beta)
{
    extern __shared__ __align__(16) float sm[];
    float* s_s  = sm + SO_S;
    float* s_ea = sm + SO_EA;
    float* s_eb = sm + SO_EB;
    ull*   Wt2  = (ull*)(sm + SO_WT);        // [j*64 + i] duplicated pairs
    float* Whs  = sm + SO_WHS;               // [2][64*48]
    int*   adjb = (int*)(sm + SO_ADJ);       // [2][64*68]
    float* Zs   = sm + SO_ZS;                // [2][64]

    int tid = threadIdx.x;
    int I0 = blockIdx.x * TIA;

    // build-phase coords
    int irel = tid & 63, ghalf = tid >> 6;
    // fma-phase coords: 4 rows x 6 dims per thread
    int tx = tid & 7, ty = tid >> 3;
    int d0 = tx * 6;

    // ---- prologue: async-load tables + tile 0 ----
#pragma unroll
    for (int p = 0; p < 16; p++) {
        int idx = tid + p * 128;             // 2048 chunks per table
        cpa16(s_s  + idx * 4, g_s  + idx * 4);
        cpa16(s_ea + idx * 4, g_ea + idx * 4);
        cpa16(s_eb + idx * 4, g_eb + idx * 4);
    }
    issue_whs(Whs, 0, tid);
    issue_adj(adjb, adj, I0, 0, tid);
    cpa_commit();

    ull acc[4][3];
#pragma unroll
    for (int r = 0; r < 4; r++)
#pragma unroll
        for (int q = 0; q < 3; q++) acc[r][q] = 0ull;
    float Zacc = 0.f;

    cpa_wait0();
    __syncthreads();
    float si = s_s[I0 + irel], eai = s_ea[I0 + irel], ebi = s_eb[I0 + irel];

    for (int t = 0; t < NN / TJA; t++) {
        int buf = t & 1;
        // issue copies for next tile (wraps harmlessly on last)
        int Jn = ((t + 1) & (NN / TJA - 1)) * TJA;
        issue_whs(Whs + (buf ^ 1) * (TJA * DH), Jn, tid);
        issue_adj(adjb + (buf ^ 1) * (TIA * ADJP), adj, I0, Jn, tid);
        cpa_commit();

        // ---- build weight tile (pre-duplicated pairs) + Z partials ----
        int J0 = t * TJA;
        const int* ab = adjb + buf * (TIA * ADJP) + irel * ADJP;
#pragma unroll
        for (int it = 0; it < 8; it++) {
            int g = ghalf + it * 2;          // 0..15
            int j0 = g * 4;
            int4   a4  = *(const int4*)(ab + j0);
            float4 sj  = *(const float4*)(s_s  + J0 + j0);
            float4 eaj = *(const float4*)(s_ea + J0 + j0);
            float4 ebj = *(const float4*)(s_eb + J0 + j0);
            float w0 = (si + sj.x > 0.f) ? (eai * eaj.x) : (ebi * ebj.x); if (!a4.x) w0 = 0.f;
            float w1 = (si + sj.y > 0.f) ? (eai * eaj.y) : (ebi * ebj.y); if (!a4.y) w1 = 0.f;
            float w2 = (si + sj.z > 0.f) ? (eai * eaj.z) : (ebi * ebj.z); if (!a4.z) w2 = 0.f;
            float w3 = (si + sj.w > 0.f) ? (eai * eaj.w) : (ebi * ebj.w); if (!a4.w) w3 = 0.f;
            Zacc += (w0 + w1) + (w2 + w3);
            ((float2*)Wt2)[(j0 + 0) * TIA + irel] = make_float2(w0, w0);
            ((float2*)Wt2)[(j0 + 1) * TIA + irel] = make_float2(w1, w1);
            ((float2*)Wt2)[(j0 + 2) * TIA + irel] = make_float2(w2, w2);
            ((float2*)Wt2)[(j0 + 3) * TIA + irel] = make_float2(w3, w3);
        }
        __syncthreads();                     // Wt2 ready

        // ---- FMA mainloop: acc[r][:] += w[j][row] * Wh[j][dims] ----
        const float* wh = Whs + buf * (TJA * DH) + d0;
#pragma unroll 4
        for (int j = 0; j < TJA; j++) {
            const ull* wp = Wt2 + j * TIA + ty * 4;
            ull w0 = wp[0], w1 = wp[1], w2 = wp[2], w3 = wp[3];
            const float* up = wh + j * DH;
            ull u0 = *(const ull*)(up);
            ull u1 = *(const ull*)(up + 2);
            ull u2 = *(const ull*)(up + 4);
            ffma2(acc[0][0], w0, u0); ffma2(acc[0][1], w0, u1); ffma2(acc[0][2], w0, u2);
            ffma2(acc[1][0], w1, u0); ffma2(acc[1][1], w1, u1); ffma2(acc[1][2], w1, u2);
            ffma2(acc[2][0], w2, u0); ffma2(acc[2][1], w2, u1); ffma2(acc[2][2], w2, u2);
            ffma2(acc[3][0], w3, u0); ffma2(acc[3][1], w3, u1); ffma2(acc[3][2], w3, u2);
        }
        cpa_wait0();                         // next tile's copies landed
        __syncthreads();                     // FMA done -> Wt2/bufs reusable
    }

    // ---- epilogue: normalize by Z, then fused LayerNorm ----
    Zs[ghalf * TIA + irel] = Zacc;
    __syncthreads();

    float gam[6], bet[6];
#pragma unroll
    for (int k = 0; k < 6; k++) { gam[k] = gamma[d0 + k]; bet[k] = beta[d0 + k]; }

#pragma unroll
    for (int r = 0; r < 4; r++) {
        int row = ty * 4 + r;
        float rz = 1.0f / (Zs[row] + Zs[TIA + row]);
        float v[6];
#pragma unroll
        for (int q = 0; q < 3; q++) {
            float2 p = *reinterpret_cast<float2*>(&acc[r][q]);
            v[q * 2 + 0] = p.x * rz;
            v[q * 2 + 1] = p.y * rz;
        }
        float s1 = ((v[0] + v[1]) + (v[2] + v[3])) + (v[4] + v[5]);
        s1 += __shfl_xor_sync(0xffffffffu, s1, 1);
        s1 += __shfl_xor_sync(0xffffffffu, s1, 2);
        s1 += __shfl_xor_sync(0xffffffffu, s1, 4);
        float mu = s1 * (1.0f / DH);
        float s2 = 0.f;
#pragma unroll
        for (int k = 0; k < 6; k++) { float d = v[k] - mu; s2 += d * d; }
        s2 += __shfl_xor_sync(0xffffffffu, s2, 1);
        s2 += __shfl_xor_sync(0xffffffffu, s2, 2);
        s2 += __shfl_xor_sync(0xffffffffu, s2, 4);
        float rstd = rsqrtf(s2 * (1.0f / DH) + 1e-5f);

        float* op = g_hn + (size_t)(I0 + row) * DH + d0;
#pragma unroll
        for (int q = 0; q < 3; q++) {
            float2 o;
            o.x = (v[q * 2 + 0] - mu) * rstd * gam[q * 2 + 0] + bet[q * 2 + 0];
            o.y = (v[q * 2 + 1] - mu) * rstd * gam[q * 2 + 1] + bet[q * 2 + 1];
            *(float2*)(op + 2 * q) = o;
        }
    }
}

// ------------------------- launch ------------------------------------------
extern "C" void kernel_launch(void* const* d_in, const int* in_sizes, int n_in,
                              void* d_out, int out_size)
{
    const float* x     = (const float*)d_in[0];
    const int*   adj   = (const int*)  d_in[1];
    const float* Wg    = (const float*)d_in[2];
    const float* avec  = (const float*)d_in[3];
    const float* gamma = (const float*)d_in[4];
    const float* beta  = (const float*)d_in[5];
    const float* W1    = (const float*)d_in[6];
    const float* b1    = (const float*)d_in[7];
    const float* W2    = (const float*)d_in[8];
    const float* b2    = (const float*)d_in[9];
    const float* W3    = (const float*)d_in[10];
    const float* b3    = (const float*)d_in[11];
    float* out = (float*)d_out;

    float *Wh, *hn, *m1, *m2;
    cudaGetSymbolAddress((void**)&Wh, g_Wh);
    cudaGetSymbolAddress((void**)&hn, g_hn);
    cudaGetSymbolAddress((void**)&m1, g_m1);
    cudaGetSymbolAddress((void**)&m2, g_m2);

    static int smem_set = 0;
    if (!smem_set) {
        cudaFuncSetAttribute(attn_kernel,
                             cudaFuncAttributeMaxDynamicSharedMemorySize,
                             SMEM_FLOATS * 4);
        smem_set = 1;
    }

    // Wh = x @ W_gat^T   [8192 x 48]
    gemm_kernel<<<dim3(1, NN / 64), 256>>>(x, Wg, nullptr, Wh, NN, DH, DIN, 0);
    // s, exp(s), exp(0.2 s)
    sab_kernel<<<NN / 256, 256>>>(avec);
    // fused attention + LayerNorm -> g_hn
    attn_kernel<<<NN / TIA, 128, SMEM_FLOATS * 4>>>(adj, gamma, beta);
    // MLP head
    gemm_kernel<<<dim3(DH1 / 64, NN / 64), 256>>>(hn, W1, b1, m1, NN, DH1, DH, 1);
    gemm_kernel<<<dim3(DH2 / 64, NN / 64), 256>>>(m1, W2, b2, m2, NN, DH2, DH1, 1);
    gemm_kernel<<<dim3(1, NN / 64), 256>>>(m2, W3, b3, out, NN, DOUT, DH2, 0);
}

// round 7
// speedup vs baseline: 1.2744x; 1.0224x over previous
#include <cuda_runtime.h>
#include <cuda_bf16.h>
#include <math.h>
#include <stdint.h>

#define NN   8192
#define DIN  128
#define DH   48
#define DH1  256
#define DH2  128
#define DOUT 32

#define KSPLIT  2
#define TTILES  64            // j-tiles of 64 per K-half

typedef unsigned int u32;

// ------------------------- scratch (device globals; no allocs) -------------
__device__ float g_Wh[NN * DH];
__device__ float g_s[NN];
__device__ float g_ea[NN];
__device__ float g_eb[NN];
__device__ __align__(16) u32 g_Bsw[128 * 4096];  // per-tile swizzled B hi/lo (2 MB)
__device__ float g_part[128 * 128 * 64];         // per-CTA partial D (Z at col 48)
__device__ float g_hn[NN * DH];
__device__ float g_m1[NN * DH1];
__device__ float g_m2[NN * DH2];

// ------------------------- PTX helpers -------------------------------------
__device__ __forceinline__ void cpa16(void* dst_smem, const void* src) {
    u32 d = (u32)__cvta_generic_to_shared(dst_smem);
    asm volatile("cp.async.cg.shared.global [%0], [%1], 16;" :: "r"(d), "l"(src));
}
__device__ __forceinline__ void cpa_commit() {
    asm volatile("cp.async.commit_group;" ::: "memory");
}
__device__ __forceinline__ void cpa_wait0() {
    asm volatile("cp.async.wait_group 0;" ::: "memory");
}
__device__ __forceinline__ void mma16816(float* d, u32 a0, u32 a1, u32 a2, u32 a3,
                                         u32 b0, u32 b1) {
    asm volatile(
        "mma.sync.aligned.m16n8k16.row.col.f32.bf16.bf16.f32 "
        "{%0,%1,%2,%3}, {%4,%5,%6,%7}, {%8,%9}, {%0,%1,%2,%3};"
        : "+f"(d[0]), "+f"(d[1]), "+f"(d[2]), "+f"(d[3])
        : "r"(a0), "r"(a1), "r"(a2), "r"(a3), "r"(b0), "r"(b1));
}

// ------------------------- generic tiled GEMM (known-good) -----------------
__global__ void __launch_bounds__(256) gemm_kernel(
    const float* __restrict__ A, const float* __restrict__ W,
    const float* __restrict__ bias, float* __restrict__ C,
    int M, int Nn, int K, int relu)
{
    __shared__ __align__(16) float As[16][68];
    __shared__ __align__(16) float Ws[16][68];

    int tid = threadIdx.x;
    int tx = tid & 15, ty = tid >> 4;
    int m0 = blockIdx.y * 64, n0 = blockIdx.x * 64;

    float acc[4][4];
#pragma unroll
    for (int r = 0; r < 4; r++)
#pragma unroll
        for (int c = 0; c < 4; c++) acc[r][c] = 0.f;

    int lr = tid >> 2;
    int lc = (tid & 3) * 4;
    const float* Ap = A + (size_t)(m0 + lr) * K + lc;
    bool wvalid = (n0 + lr) < Nn;
    const float* Wp = W + (size_t)(n0 + lr) * K + lc;

    for (int k0 = 0; k0 < K; k0 += 16) {
        float4 av = *(const float4*)(Ap + k0);
        float4 wv = wvalid ? *(const float4*)(Wp + k0) : make_float4(0.f, 0.f, 0.f, 0.f);
        __syncthreads();
        As[lc + 0][lr] = av.x; As[lc + 1][lr] = av.y;
        As[lc + 2][lr] = av.z; As[lc + 3][lr] = av.w;
        Ws[lc + 0][lr] = wv.x; Ws[lc + 1][lr] = wv.y;
        Ws[lc + 2][lr] = wv.z; Ws[lc + 3][lr] = wv.w;
        __syncthreads();
#pragma unroll
        for (int kk = 0; kk < 16; kk++) {
            float4 a4 = *(const float4*)&As[kk][ty * 4];
            float4 b4 = *(const float4*)&Ws[kk][tx * 4];
            acc[0][0] = fmaf(a4.x, b4.x, acc[0][0]);
            acc[0][1] = fmaf(a4.x, b4.y, acc[0][1]);
            acc[0][2] = fmaf(a4.x, b4.z, acc[0][2]);
            acc[0][3] = fmaf(a4.x, b4.w, acc[0][3]);
            acc[1][0] = fmaf(a4.y, b4.x, acc[1][0]);
            acc[1][1] = fmaf(a4.y, b4.y, acc[1][1]);
            acc[1][2] = fmaf(a4.y, b4.z, acc[1][2]);
            acc[1][3] = fmaf(a4.y, b4.w, acc[1][3]);
            acc[2][0] = fmaf(a4.z, b4.x, acc[2][0]);
            acc[2][1] = fmaf(a4.z, b4.y, acc[2][1]);
            acc[2][2] = fmaf(a4.z, b4.z, acc[2][2]);
            acc[2][3] = fmaf(a4.z, b4.w, acc[2][3]);
            acc[3][0] = fmaf(a4.w, b4.x, acc[3][0]);
            acc[3][1] = fmaf(a4.w, b4.y, acc[3][1]);
            acc[3][2] = fmaf(a4.w, b4.z, acc[3][2]);
            acc[3][3] = fmaf(a4.w, b4.w, acc[3][3]);
        }
    }
#pragma unroll
    for (int r = 0; r < 4; r++) {
        int m = m0 + ty * 4 + r;
#pragma unroll
        for (int c = 0; c < 4; c++) {
            int n = n0 + tx * 4 + c;
            if (n < Nn) {
                float v = acc[r][c] + (bias ? bias[n] : 0.f);
                if (relu) v = fmaxf(v, 0.f);
                C[(size_t)m * Nn + n] = v;
            }
        }
    }
}

// --------- s/exp tables + per-tile swizzled bf16-split B --------------------
// B layout per j-tile tau (4096 u32 words): hi[64 rows d][32 words] then lo.
// word (d, w) stored at d*32 + (w ^ (4*(d&7)))  -- row-XOR swizzle.
__global__ void __launch_bounds__(256) sab_kernel(const float* __restrict__ avec)
{
    int j = blockIdx.x * blockDim.x + threadIdx.x;
    float v[DH];
    const float4* w4 = (const float4*)(g_Wh + (size_t)j * DH);
    float acc = 0.f;
#pragma unroll
    for (int q = 0; q < DH / 4; q++) {
        float4 wv = w4[q];
        float4 av = ((const float4*)avec)[q];
        v[q * 4 + 0] = wv.x; v[q * 4 + 1] = wv.y;
        v[q * 4 + 2] = wv.z; v[q * 4 + 3] = wv.w;
        acc += wv.x * av.x + wv.y * av.y + wv.z * av.z + wv.w * av.w;
    }
    g_s[j]  = acc;
    g_ea[j] = expf(acc);
    g_eb[j] = expf(0.2f * acc);

    int tau = j >> 6, jloc = j & 63;
    int half = jloc & 1, w = jloc >> 1;
    __nv_bfloat16* B = (__nv_bfloat16*)g_Bsw;
    size_t base2 = (size_t)tau * 8192;            // bf16 index of tile start
#pragma unroll
    for (int d = 0; d < DH; d++) {
        int widx = d * 32 + (w ^ (4 * (d & 7)));
        __nv_bfloat16 hi = __float2bfloat16(v[d]);
        __nv_bfloat16 lo = __float2bfloat16(v[d] - __bfloat162float(hi));
        B[base2 + widx * 2 + half] = hi;
        B[base2 + 4096 + widx * 2 + half] = lo;
    }
    {   // Z ones column at d=48
        int widx = 48 * 32 + w;                   // 48&7 == 0
        B[base2 + widx * 2 + half] = __float2bfloat16(1.0f);
        B[base2 + 4096 + widx * 2 + half] = __float2bfloat16(0.0f);
    }
#pragma unroll
    for (int d = 49; d < 64; d++) {
        int widx = d * 32 + (w ^ (4 * (d & 7)));
        B[base2 + widx * 2 + half] = __float2bfloat16(0.0f);
        B[base2 + 4096 + widx * 2 + half] = __float2bfloat16(0.0f);
    }
}

// ------------------------- HMMA attention ----------------------------------
// SMEM (bytes)
#define SM_ISL 0                    // si[128]@0 eai@512 ebi@1024
#define SM_JSL 1536                 // 2 stages x 768 (sj@0 eaj@256 ebj@512)
#define SM_AHI 4096                 // 128 rows x 128B (swizzled bf16 pairs)
#define SM_ALO 20480
#define SM_B   36864                // 2 stages x 16KB (hi 8K + lo 8K)
#define SM_TOTAL 69632

__global__ void __launch_bounds__(256, 1) attn_hmma_kernel(const int* __restrict__ adj)
{
    extern __shared__ __align__(16) char sm[];
    int tid = threadIdx.x;
    int bx = blockIdx.x;
    int I0 = (bx >> 1) * 128;
    int jhalf = bx & 1;
    int tau0 = jhalf * TTILES;
    int jbase = jhalf * (NN / KSPLIT);

    // prologue: i-slice + tile-0 B + tile-0 j-slice
    if (tid < 96) {
        int table = tid >> 5, idx = tid & 31;
        const float* tp = (table == 0) ? g_s : (table == 1) ? g_ea : g_eb;
        cpa16(sm + SM_ISL + table * 512 + idx * 16, tp + I0 + idx * 4);
    }
    {
        const u32* src = g_Bsw + (size_t)tau0 * 4096;
#pragma unroll
        for (int k = 0; k < 4; k++) {
            int chunk = tid + k * 256;
            cpa16(sm + SM_B + chunk * 16, src + chunk * 4);
        }
        if (tid < 48) {
            int table = tid >> 4, idx = tid & 15;
            const float* tp = (table == 0) ? g_s : (table == 1) ? g_ea : g_eb;
            cpa16(sm + SM_JSL + table * 256 + idx * 16, tp + tau0 * 64 + idx * 4);
        }
    }
    cpa_commit();

    // adj prefetch tile 0 (registers)
    int4 adjc[8];
#pragma unroll
    for (int p = 0; p < 8; p++) {
        int idx = tid + p * 256;
        int row = idx >> 4, c4 = (idx & 15) << 2;
        adjc[p] = *(const int4*)(adj + (size_t)(I0 + row) * NN + jbase + c4);
    }

    // mma coords
    int lane = tid & 31, warp = tid >> 5;
    int gid = lane >> 2, tig = lane & 3;
    const char* Arh = sm + SM_AHI + (warp * 16 + gid) * 128;
    const char* Arl = sm + SM_ALO + (warp * 16 + gid) * 128;
    int swz = 4 * gid;

    float acc[7][4];
#pragma unroll
    for (int nb = 0; nb < 7; nb++)
#pragma unroll
        for (int q = 0; q < 4; q++) acc[nb][q] = 0.f;

    for (int t = 0; t < TTILES; t++) {
        int s = t & 1;
        cpa_wait0();
        __syncthreads();             // B(t)/jsl(t) visible; A free to rebuild

        // ---- build A(t): weights -> bf16 hi/lo, swizzled ----
        const char* jsl = sm + SM_JSL + s * 768;
#pragma unroll
        for (int p = 0; p < 8; p++) {
            int idx = tid + p * 256;
            int row = idx >> 4, c4 = (idx & 15) << 2;
            float si  = ((const float*)(sm + SM_ISL))[row];
            float eai = ((const float*)(sm + SM_ISL + 512))[row];
            float ebi = ((const float*)(sm + SM_ISL + 1024))[row];
            float4 sj  = *(const float4*)(jsl + c4 * 4);
            float4 eaj = *(const float4*)(jsl + 256 + c4 * 4);
            float4 ebj = *(const float4*)(jsl + 512 + c4 * 4);
            int4 a = adjc[p];
            float w0 = (si + sj.x > 0.f) ? (eai * eaj.x) : (ebi * ebj.x); if (!a.x) w0 = 0.f;
            float w1 = (si + sj.y > 0.f) ? (eai * eaj.y) : (ebi * ebj.y); if (!a.y) w1 = 0.f;
            float w2 = (si + sj.z > 0.f) ? (eai * eaj.z) : (ebi * ebj.z); if (!a.z) w2 = 0.f;
            float w3 = (si + sj.w > 0.f) ? (eai * eaj.w) : (ebi * ebj.w); if (!a.w) w3 = 0.f;

            __nv_bfloat162 hA = __floats2bfloat162_rn(w0, w1);
            __nv_bfloat162 hB = __floats2bfloat162_rn(w2, w3);
            __nv_bfloat162 lA = __floats2bfloat162_rn(w0 - __bfloat162float(hA.x),
                                                      w1 - __bfloat162float(hA.y));
            __nv_bfloat162 lB = __floats2bfloat162_rn(w2 - __bfloat162float(hB.x),
                                                      w3 - __bfloat162float(hB.y));
            u32 ws = (u32)((c4 >> 1) ^ (4 * (row & 7)));
            uint2 hv, lv;
            hv.x = *reinterpret_cast<u32*>(&hA); hv.y = *reinterpret_cast<u32*>(&hB);
            lv.x = *reinterpret_cast<u32*>(&lA); lv.y = *reinterpret_cast<u32*>(&lB);
            *(uint2*)(sm + SM_AHI + row * 128 + ws * 4) = hv;
            *(uint2*)(sm + SM_ALO + row * 128 + ws * 4) = lv;
        }

        // adj prefetch for t+1 (adjc consumed; reuse in place)
        if (t + 1 < TTILES) {
            int j2 = jbase + (t + 1) * 64;
#pragma unroll
            for (int p = 0; p < 8; p++) {
                int idx = tid + p * 256;
                int row = idx >> 4, c4 = (idx & 15) << 2;
                adjc[p] = *(const int4*)(adj + (size_t)(I0 + row) * NN + j2 + c4);
            }
        }

        __syncthreads();             // A complete; all warps past mma(t-1)

        // issue copies for tile t+1 into stage s^1
        if (t + 1 < TTILES) {
            const u32* src = g_Bsw + (size_t)(tau0 + t + 1) * 4096;
            char* Bst = sm + SM_B + (s ^ 1) * 16384;
#pragma unroll
            for (int k = 0; k < 4; k++) {
                int chunk = tid + k * 256;
                cpa16(Bst + chunk * 16, src + chunk * 4);
            }
            if (tid < 48) {
                int table = tid >> 4, idx = tid & 15;
                const float* tp = (table == 0) ? g_s : (table == 1) ? g_ea : g_eb;
                cpa16(sm + SM_JSL + (s ^ 1) * 768 + table * 256 + idx * 16,
                      tp + (tau0 + t + 1) * 64 + idx * 4);
            }
            cpa_commit();
        }

        // ---- HMMA mainloop over this tile ----
        const char* Bs = sm + SM_B + s * 16384;
#pragma unroll
        for (int c = 0; c < 4; c++) {
            int wA = c * 8 + tig;
            u32 o1 = (u32)((wA ^ swz) * 4);
            u32 o2 = (u32)(((wA + 4) ^ swz) * 4);
            u32 ah0 = *(const u32*)(Arh + o1);
            u32 ah1 = *(const u32*)(Arh + 1024 + o1);
            u32 ah2 = *(const u32*)(Arh + o2);
            u32 ah3 = *(const u32*)(Arh + 1024 + o2);
            u32 al0 = *(const u32*)(Arl + o1);
            u32 al1 = *(const u32*)(Arl + 1024 + o1);
            u32 al2 = *(const u32*)(Arl + o2);
            u32 al3 = *(const u32*)(Arl + 1024 + o2);
#pragma unroll
            for (int nb = 0; nb < 7; nb++) {
                const char* Bn = Bs + (nb * 8 + gid) * 128;
                u32 bh0 = *(const u32*)(Bn + o1);
                u32 bh1 = *(const u32*)(Bn + o2);
                u32 bl0 = *(const u32*)(Bn + 8192 + o1);
                u32 bl1 = *(const u32*)(Bn + 8192 + o2);
                mma16816(acc[nb], ah0, ah1, ah2, ah3, bh0, bh1);
                mma16816(acc[nb], ah0, ah1, ah2, ah3, bl0, bl1);
                mma16816(acc[nb], al0, al1, al2, al3, bh0, bh1);
            }
        }
    }

    // ---- epilogue: write partials ----
    float* dst = g_part + ((size_t)bx * 128 + warp * 16 + gid) * 64;
#pragma unroll
    for (int nb = 0; nb < 7; nb++) {
        int col = nb * 8 + tig * 2;
        float2 lo = make_float2(acc[nb][0], acc[nb][1]);
        float2 hi = make_float2(acc[nb][2], acc[nb][3]);
        *(float2*)(dst + col) = lo;
        *(float2*)(dst + 8 * 64 + col) = hi;
    }
}

// -------------------- reduce K-split + normalize + LayerNorm ----------------
__global__ void __launch_bounds__(64) reduce_ln_kernel(
    const float* __restrict__ gamma, const float* __restrict__ beta)
{
    int i = blockIdx.x * 64 + threadIdx.x;
    int itile = i >> 7, r = i & 127;
    const float* p0 = g_part + ((size_t)(itile * 2 + 0) * 128 + r) * 64;
    const float* p1 = g_part + ((size_t)(itile * 2 + 1) * 128 + r) * 64;

    float v[52];
#pragma unroll
    for (int q = 0; q < 13; q++) {
        float4 a = ((const float4*)p0)[q];
        float4 b = ((const float4*)p1)[q];
        v[q * 4 + 0] = a.x + b.x;
        v[q * 4 + 1] = a.y + b.y;
        v[q * 4 + 2] = a.z + b.z;
        v[q * 4 + 3] = a.w + b.w;
    }
    float rz = 1.0f / v[48];
    float h[DH];
    float s1 = 0.f;
#pragma unroll
    for (int d = 0; d < DH; d++) { h[d] = v[d] * rz; s1 += h[d]; }
    float mu = s1 * (1.0f / DH);
    float s2 = 0.f;
#pragma unroll
    for (int d = 0; d < DH; d++) { float dd = h[d] - mu; s2 += dd * dd; }
    float rstd = rsqrtf(s2 * (1.0f / DH) + 1e-5f);
    float* o = g_hn + (size_t)i * DH;
#pragma unroll
    for (int d = 0; d < DH; d++)
        o[d] = (h[d] - mu) * rstd * gamma[d] + beta[d];
}

// ------------------------- launch ------------------------------------------
extern "C" void kernel_launch(void* const* d_in, const int* in_sizes, int n_in,
                              void* d_out, int out_size)
{
    const float* x     = (const float*)d_in[0];
    const int*   adj   = (const int*)  d_in[1];
    const float* Wg    = (const float*)d_in[2];
    const float* avec  = (const float*)d_in[3];
    const float* gamma = (const float*)d_in[4];
    const float* beta  = (const float*)d_in[5];
    const float* W1    = (const float*)d_in[6];
    const float* b1    = (const float*)d_in[7];
    const float* W2    = (const float*)d_in[8];
    const float* b2    = (const float*)d_in[9];
    const float* W3    = (const float*)d_in[10];
    const float* b3    = (const float*)d_in[11];
    float* out = (float*)d_out;

    float *Wh, *hn, *m1, *m2;
    cudaGetSymbolAddress((void**)&Wh, g_Wh);
    cudaGetSymbolAddress((void**)&hn, g_hn);
    cudaGetSymbolAddress((void**)&m1, g_m1);
    cudaGetSymbolAddress((void**)&m2, g_m2);

    static int smem_set = 0;
    if (!smem_set) {
        cudaFuncSetAttribute(attn_hmma_kernel,
                             cudaFuncAttributeMaxDynamicSharedMemorySize, SM_TOTAL);
        smem_set = 1;
    }

    // Wh = x @ W_gat^T   [8192 x 48]
    gemm_kernel<<<dim3(1, NN / 64), 256>>>(x, Wg, nullptr, Wh, NN, DH, DIN, 0);
    // s, exp tables, per-tile swizzled bf16-split B
    sab_kernel<<<NN / 256, 256>>>(avec);
    // tensor-core (HMMA) attention -> g_part
    attn_hmma_kernel<<<128, 256, SM_TOTAL>>>(adj);
    // combine K-halves, normalize, LayerNorm -> g_hn
    reduce_ln_kernel<<<128, 64>>>(gamma, beta);
    // MLP head
    gemm_kernel<<<dim3(DH1 / 64, NN / 64), 256>>>(hn, W1, b1, m1, NN, DH1, DH, 1);
    gemm_kernel<<<dim3(DH2 / 64, NN / 64), 256>>>(m1, W2, b2, m2, NN, DH2, DH1, 1);
    gemm_kernel<<<dim3(1, NN / 64), 256>>>(m2, W3, b3, out, NN, DOUT, DH2, 0);
}

// round 8
// speedup vs baseline: 2.2707x; 1.7818x over previous
#include <cuda_runtime.h>
#include <cuda_bf16.h>
#include <math.h>
#include <stdint.h>

#define NN   8192
#define DIN  128
#define DH   48
#define DH1  256
#define DH2  128
#define DOUT 32

#define KSPLIT  4
#define TTILES  32            // j-tiles of 64 per K-quarter

typedef unsigned int u32;

// ------------------------- scratch (device globals; no allocs) -------------
__device__ float g_Wh[NN * DH];
__device__ float g_s[NN];
__device__ float g_ea[NN];
__device__ float g_eb[NN];
__device__ __align__(16) u32 g_Bsw[128 * 4096];  // per-tile swizzled B hi/lo (2 MB)
__device__ float g_part[256 * 128 * 64];         // per-CTA partial D (Z at col 48)
__device__ float g_hn[NN * DH];
__device__ float g_m1[NN * DH1];
__device__ float g_m2[NN * DH2];

// ------------------------- PTX helpers -------------------------------------
__device__ __forceinline__ void cpa16(void* dst_smem, const void* src) {
    u32 d = (u32)__cvta_generic_to_shared(dst_smem);
    asm volatile("cp.async.cg.shared.global [%0], [%1], 16;" :: "r"(d), "l"(src));
}
__device__ __forceinline__ void cpa_commit() {
    asm volatile("cp.async.commit_group;" ::: "memory");
}
__device__ __forceinline__ void cpa_wait0() {
    asm volatile("cp.async.wait_group 0;" ::: "memory");
}
__device__ __forceinline__ void mma16816(float* d, u32 a0, u32 a1, u32 a2, u32 a3,
                                         u32 b0, u32 b1) {
    asm volatile(
        "mma.sync.aligned.m16n8k16.row.col.f32.bf16.bf16.f32 "
        "{%0,%1,%2,%3}, {%4,%5,%6,%7}, {%8,%9}, {%0,%1,%2,%3};"
        : "+f"(d[0]), "+f"(d[1]), "+f"(d[2]), "+f"(d[3])
        : "r"(a0), "r"(a1), "r"(a2), "r"(a3), "r"(b0), "r"(b1));
}

// ------------------------- generic tiled GEMM (known-good) -----------------
__global__ void __launch_bounds__(256) gemm_kernel(
    const float* __restrict__ A, const float* __restrict__ W,
    const float* __restrict__ bias, float* __restrict__ C,
    int M, int Nn, int K, int relu)
{
    __shared__ __align__(16) float As[16][68];
    __shared__ __align__(16) float Ws[16][68];

    int tid = threadIdx.x;
    int tx = tid & 15, ty = tid >> 4;
    int m0 = blockIdx.y * 64, n0 = blockIdx.x * 64;

    float acc[4][4];
#pragma unroll
    for (int r = 0; r < 4; r++)
#pragma unroll
        for (int c = 0; c < 4; c++) acc[r][c] = 0.f;

    int lr = tid >> 2;
    int lc = (tid & 3) * 4;
    const float* Ap = A + (size_t)(m0 + lr) * K + lc;
    bool wvalid = (n0 + lr) < Nn;
    const float* Wp = W + (size_t)(n0 + lr) * K + lc;

    for (int k0 = 0; k0 < K; k0 += 16) {
        float4 av = *(const float4*)(Ap + k0);
        float4 wv = wvalid ? *(const float4*)(Wp + k0) : make_float4(0.f, 0.f, 0.f, 0.f);
        __syncthreads();
        As[lc + 0][lr] = av.x; As[lc + 1][lr] = av.y;
        As[lc + 2][lr] = av.z; As[lc + 3][lr] = av.w;
        Ws[lc + 0][lr] = wv.x; Ws[lc + 1][lr] = wv.y;
        Ws[lc + 2][lr] = wv.z; Ws[lc + 3][lr] = wv.w;
        __syncthreads();
#pragma unroll
        for (int kk = 0; kk < 16; kk++) {
            float4 a4 = *(const float4*)&As[kk][ty * 4];
            float4 b4 = *(const float4*)&Ws[kk][tx * 4];
            acc[0][0] = fmaf(a4.x, b4.x, acc[0][0]);
            acc[0][1] = fmaf(a4.x, b4.y, acc[0][1]);
            acc[0][2] = fmaf(a4.x, b4.z, acc[0][2]);
            acc[0][3] = fmaf(a4.x, b4.w, acc[0][3]);
            acc[1][0] = fmaf(a4.y, b4.x, acc[1][0]);
            acc[1][1] = fmaf(a4.y, b4.y, acc[1][1]);
            acc[1][2] = fmaf(a4.y, b4.z, acc[1][2]);
            acc[1][3] = fmaf(a4.y, b4.w, acc[1][3]);
            acc[2][0] = fmaf(a4.z, b4.x, acc[2][0]);
            acc[2][1] = fmaf(a4.z, b4.y, acc[2][1]);
            acc[2][2] = fmaf(a4.z, b4.z, acc[2][2]);
            acc[2][3] = fmaf(a4.z, b4.w, acc[2][3]);
            acc[3][0] = fmaf(a4.w, b4.x, acc[3][0]);
            acc[3][1] = fmaf(a4.w, b4.y, acc[3][1]);
            acc[3][2] = fmaf(a4.w, b4.z, acc[3][2]);
            acc[3][3] = fmaf(a4.w, b4.w, acc[3][3]);
        }
    }
#pragma unroll
    for (int r = 0; r < 4; r++) {
        int m = m0 + ty * 4 + r;
#pragma unroll
        for (int c = 0; c < 4; c++) {
            int n = n0 + tx * 4 + c;
            if (n < Nn) {
                float v = acc[r][c] + (bias ? bias[n] : 0.f);
                if (relu) v = fmaxf(v, 0.f);
                C[(size_t)m * Nn + n] = v;
            }
        }
    }
}

// --------- s/exp tables + per-tile swizzled bf16-split B --------------------
// B layout per j-tile tau (4096 u32): hi[64 rows d][32 words] then lo.
// word (d, w) at d*32 + (w ^ (4*(d&7))). Scatter into SMEM, coalesced write-out.
__global__ void __launch_bounds__(256) sab_kernel(const float* __restrict__ avec)
{
    extern __shared__ __align__(16) u32 st[];        // 4 taus x 4096 u32 = 64KB
    int tid = threadIdx.x;
    int j = blockIdx.x * 256 + tid;

    float v[DH];
    const float4* w4 = (const float4*)(g_Wh + (size_t)j * DH);
    float acc = 0.f;
#pragma unroll
    for (int q = 0; q < DH / 4; q++) {
        float4 wv = w4[q];
        float4 av = ((const float4*)avec)[q];
        v[q * 4 + 0] = wv.x; v[q * 4 + 1] = wv.y;
        v[q * 4 + 2] = wv.z; v[q * 4 + 3] = wv.w;
        acc += wv.x * av.x + wv.y * av.y + wv.z * av.z + wv.w * av.w;
    }
    g_s[j]  = acc;
    g_ea[j] = expf(acc);
    g_eb[j] = expf(0.2f * acc);

    int tau_l = tid >> 6, jloc = tid & 63;
    int half = jloc & 1, w = jloc >> 1;
    __nv_bfloat16* B = (__nv_bfloat16*)st + tau_l * 8192;
#pragma unroll
    for (int d = 0; d < DH; d++) {
        int widx = d * 32 + (w ^ (4 * (d & 7)));
        __nv_bfloat16 hi = __float2bfloat16(v[d]);
        __nv_bfloat16 lo = __float2bfloat16(v[d] - __bfloat162float(hi));
        B[widx * 2 + half] = hi;
        B[4096 + widx * 2 + half] = lo;
    }
    {   // Z ones column at d=48 (48&7 == 0 -> no swizzle shift)
        int widx = 48 * 32 + w;
        B[widx * 2 + half] = __float2bfloat16(1.0f);
        B[4096 + widx * 2 + half] = __float2bfloat16(0.0f);
    }
#pragma unroll
    for (int d = 49; d < 64; d++) {
        int widx = d * 32 + (w ^ (4 * (d & 7)));
        B[widx * 2 + half] = __float2bfloat16(0.0f);
        B[4096 + widx * 2 + half] = __float2bfloat16(0.0f);
    }
    __syncthreads();

    // coalesced write-out: 64KB = 4096 x 16B
    uint4* dst = (uint4*)(g_Bsw + (size_t)blockIdx.x * 4 * 4096);
    const uint4* src = (const uint4*)st;
#pragma unroll
    for (int it = 0; it < 16; it++)
        dst[tid + it * 256] = src[tid + it * 256];
}

// ------------------------- HMMA attention ----------------------------------
// SMEM (bytes)
#define SM_ISL 0                    // si[128]@0 eai@512 ebi@1024
#define SM_JSL 1536                 // 2 stages x 768 (sj@0 eaj@256 ebj@512)
#define SM_AHI 4096                 // 128 rows x 128B (swizzled bf16 pairs)
#define SM_ALO 20480
#define SM_B   36864                // 2 stages x 16KB (hi 8K + lo 8K)
#define SM_TOTAL 69632

__global__ void __launch_bounds__(256, 2) attn_hmma_kernel(const int* __restrict__ adj)
{
    extern __shared__ __align__(16) char sm[];
    int tid = threadIdx.x;
    int bx = blockIdx.x;
    int I0 = (bx >> 2) * 128;
    int jq = bx & 3;
    int tau0 = jq * TTILES;
    int jbase = jq * (NN / KSPLIT);

    // prologue: i-slice + tile-0 B + tile-0 j-slice
    if (tid < 96) {
        int table = tid >> 5, idx = tid & 31;
        const float* tp = (table == 0) ? g_s : (table == 1) ? g_ea : g_eb;
        cpa16(sm + SM_ISL + table * 512 + idx * 16, tp + I0 + idx * 4);
    }
    {
        const u32* src = g_Bsw + (size_t)tau0 * 4096;
#pragma unroll
        for (int k = 0; k < 4; k++) {
            int chunk = tid + k * 256;
            cpa16(sm + SM_B + chunk * 16, src + chunk * 4);
        }
        if (tid < 48) {
            int table = tid >> 4, idx = tid & 15;
            const float* tp = (table == 0) ? g_s : (table == 1) ? g_ea : g_eb;
            cpa16(sm + SM_JSL + table * 256 + idx * 16, tp + tau0 * 64 + idx * 4);
        }
    }
    cpa_commit();

    // adj prefetch tile 0 (registers)
    int4 adjc[8];
#pragma unroll
    for (int p = 0; p < 8; p++) {
        int idx = tid + p * 256;
        int row = idx >> 4, c4 = (idx & 15) << 2;
        adjc[p] = *(const int4*)(adj + (size_t)(I0 + row) * NN + jbase + c4);
    }

    // mma coords
    int lane = tid & 31, warp = tid >> 5;
    int gid = lane >> 2, tig = lane & 3;
    const char* Arh = sm + SM_AHI + (warp * 16 + gid) * 128;
    const char* Arl = sm + SM_ALO + (warp * 16 + gid) * 128;
    int swz = 4 * gid;

    float acc[7][4];
#pragma unroll
    for (int nb = 0; nb < 7; nb++)
#pragma unroll
        for (int q = 0; q < 4; q++) acc[nb][q] = 0.f;

    for (int t = 0; t < TTILES; t++) {
        int s = t & 1;
        cpa_wait0();
        __syncthreads();             // B(t)/jsl(t) visible; A free to rebuild

        // ---- build A(t): weights -> bf16 hi/lo, swizzled ----
        const char* jsl = sm + SM_JSL + s * 768;
#pragma unroll
        for (int p = 0; p < 8; p++) {
            int idx = tid + p * 256;
            int row = idx >> 4, c4 = (idx & 15) << 2;
            float si  = ((const float*)(sm + SM_ISL))[row];
            float eai = ((const float*)(sm + SM_ISL + 512))[row];
            float ebi = ((const float*)(sm + SM_ISL + 1024))[row];
            float4 sj  = *(const float4*)(jsl + c4 * 4);
            float4 eaj = *(const float4*)(jsl + 256 + c4 * 4);
            float4 ebj = *(const float4*)(jsl + 512 + c4 * 4);
            int4 a = adjc[p];
            float w0 = (si + sj.x > 0.f) ? (eai * eaj.x) : (ebi * ebj.x); if (!a.x) w0 = 0.f;
            float w1 = (si + sj.y > 0.f) ? (eai * eaj.y) : (ebi * ebj.y); if (!a.y) w1 = 0.f;
            float w2 = (si + sj.z > 0.f) ? (eai * eaj.z) : (ebi * ebj.z); if (!a.z) w2 = 0.f;
            float w3 = (si + sj.w > 0.f) ? (eai * eaj.w) : (ebi * ebj.w); if (!a.w) w3 = 0.f;

            __nv_bfloat162 hA = __floats2bfloat162_rn(w0, w1);
            __nv_bfloat162 hB = __floats2bfloat162_rn(w2, w3);
            __nv_bfloat162 lA = __floats2bfloat162_rn(w0 - __bfloat162float(hA.x),
                                                      w1 - __bfloat162float(hA.y));
            __nv_bfloat162 lB = __floats2bfloat162_rn(w2 - __bfloat162float(hB.x),
                                                      w3 - __bfloat162float(hB.y));
            u32 ws = (u32)((c4 >> 1) ^ (4 * (row & 7)));
            uint2 hv, lv;
            hv.x = *reinterpret_cast<u32*>(&hA); hv.y = *reinterpret_cast<u32*>(&hB);
            lv.x = *reinterpret_cast<u32*>(&lA); lv.y = *reinterpret_cast<u32*>(&lB);
            *(uint2*)(sm + SM_AHI + row * 128 + ws * 4) = hv;
            *(uint2*)(sm + SM_ALO + row * 128 + ws * 4) = lv;
        }

        // adj prefetch for t+1
        if (t + 1 < TTILES) {
            int j2 = jbase + (t + 1) * 64;
#pragma unroll
            for (int p = 0; p < 8; p++) {
                int idx = tid + p * 256;
                int row = idx >> 4, c4 = (idx & 15) << 2;
                adjc[p] = *(const int4*)(adj + (size_t)(I0 + row) * NN + j2 + c4);
            }
        }

        __syncthreads();             // A complete; all warps past mma(t-1)

        // issue copies for tile t+1 into stage s^1
        if (t + 1 < TTILES) {
            const u32* src = g_Bsw + (size_t)(tau0 + t + 1) * 4096;
            char* Bst = sm + SM_B + (s ^ 1) * 16384;
#pragma unroll
            for (int k = 0; k < 4; k++) {
                int chunk = tid + k * 256;
                cpa16(Bst + chunk * 16, src + chunk * 4);
            }
            if (tid < 48) {
                int table = tid >> 4, idx = tid & 15;
                const float* tp = (table == 0) ? g_s : (table == 1) ? g_ea : g_eb;
                cpa16(sm + SM_JSL + (s ^ 1) * 768 + table * 256 + idx * 16,
                      tp + (tau0 + t + 1) * 64 + idx * 4);
            }
            cpa_commit();
        }

        // ---- HMMA mainloop over this tile ----
        const char* Bs = sm + SM_B + s * 16384;
#pragma unroll
        for (int c = 0; c < 4; c++) {
            int wA = c * 8 + tig;
            u32 o1 = (u32)((wA ^ swz) * 4);
            u32 o2 = (u32)(((wA + 4) ^ swz) * 4);
            u32 ah0 = *(const u32*)(Arh + o1);
            u32 ah1 = *(const u32*)(Arh + 1024 + o1);
            u32 ah2 = *(const u32*)(Arh + o2);
            u32 ah3 = *(const u32*)(Arh + 1024 + o2);
            u32 al0 = *(const u32*)(Arl + o1);
            u32 al1 = *(const u32*)(Arl + 1024 + o1);
            u32 al2 = *(const u32*)(Arl + o2);
            u32 al3 = *(const u32*)(Arl + 1024 + o2);
#pragma unroll
            for (int nb = 0; nb < 7; nb++) {
                const char* Bn = Bs + (nb * 8 + gid) * 128;
                u32 bh0 = *(const u32*)(Bn + o1);
                u32 bh1 = *(const u32*)(Bn + o2);
                u32 bl0 = *(const u32*)(Bn + 8192 + o1);
                u32 bl1 = *(const u32*)(Bn + 8192 + o2);
                mma16816(acc[nb], ah0, ah1, ah2, ah3, bh0, bh1);
                mma16816(acc[nb], ah0, ah1, ah2, ah3, bl0, bl1);
                mma16816(acc[nb], al0, al1, al2, al3, bh0, bh1);
            }
        }
    }

    // ---- epilogue: write partials ----
    float* dst = g_part + ((size_t)bx * 128 + warp * 16 + gid) * 64;
#pragma unroll
    for (int nb = 0; nb < 7; nb++) {
        int col = nb * 8 + tig * 2;
        *(float2*)(dst + col) = make_float2(acc[nb][0], acc[nb][1]);
        *(float2*)(dst + 8 * 64 + col) = make_float2(acc[nb][2], acc[nb][3]);
    }
}

// -------------------- reduce K-split + normalize + LayerNorm ----------------
__global__ void __launch_bounds__(128) reduce_ln_kernel(
    const float* __restrict__ gamma, const float* __restrict__ beta)
{
    int i = blockIdx.x * 128 + threadIdx.x;      // grid 64 x 128 = 8192 rows
    int itile = i >> 7, r = i & 127;
    const float* p0 = g_part + ((size_t)(itile * 4 + 0) * 128 + r) * 64;
    const float* p1 = g_part + ((size_t)(itile * 4 + 1) * 128 + r) * 64;
    const float* p2 = g_part + ((size_t)(itile * 4 + 2) * 128 + r) * 64;
    const float* p3 = g_part + ((size_t)(itile * 4 + 3) * 128 + r) * 64;

    float v[52];
#pragma unroll
    for (int q = 0; q < 13; q++) {
        float4 a = ((const float4*)p0)[q];
        float4 b = ((const float4*)p1)[q];
        float4 c = ((const float4*)p2)[q];
        float4 d = ((const float4*)p3)[q];
        v[q * 4 + 0] = (a.x + b.x) + (c.x + d.x);
        v[q * 4 + 1] = (a.y + b.y) + (c.y + d.y);
        v[q * 4 + 2] = (a.z + b.z) + (c.z + d.z);
        v[q * 4 + 3] = (a.w + b.w) + (c.w + d.w);
    }
    float rz = 1.0f / v[48];
    float h[DH];
    float s1 = 0.f;
#pragma unroll
    for (int d = 0; d < DH; d++) { h[d] = v[d] * rz; s1 += h[d]; }
    float mu = s1 * (1.0f / DH);
    float s2 = 0.f;
#pragma unroll
    for (int d = 0; d < DH; d++) { float dd = h[d] - mu; s2 += dd * dd; }
    float rstd = rsqrtf(s2 * (1.0f / DH) + 1e-5f);
    float* o = g_hn + (size_t)i * DH;
#pragma unroll
    for (int d = 0; d < DH; d++)
        o[d] = (h[d] - mu) * rstd * gamma[d] + beta[d];
}

// ------------------------- launch ------------------------------------------
extern "C" void kernel_launch(void* const* d_in, const int* in_sizes, int n_in,
                              void* d_out, int out_size)
{
    const float* x     = (const float*)d_in[0];
    const int*   adj   = (const int*)  d_in[1];
    const float* Wg    = (const float*)d_in[2];
    const float* avec  = (const float*)d_in[3];
    const float* gamma = (const float*)d_in[4];
    const float* beta  = (const float*)d_in[5];
    const float* W1    = (const float*)d_in[6];
    const float* b1    = (const float*)d_in[7];
    const float* W2    = (const float*)d_in[8];
    const float* b2    = (const float*)d_in[9];
    const float* W3    = (const float*)d_in[10];
    const float* b3    = (const float*)d_in[11];
    float* out = (float*)d_out;

    float *Wh, *hn, *m1, *m2;
    cudaGetSymbolAddress((void**)&Wh, g_Wh);
    cudaGetSymbolAddress((void**)&hn, g_hn);
    cudaGetSymbolAddress((void**)&m1, g_m1);
    cudaGetSymbolAddress((void**)&m2, g_m2);

    static int smem_set = 0;
    if (!smem_set) {
        cudaFuncSetAttribute(attn_hmma_kernel,
                             cudaFuncAttributeMaxDynamicSharedMemorySize, SM_TOTAL);
        cudaFuncSetAttribute(sab_kernel,
                             cudaFuncAttributeMaxDynamicSharedMemorySize, 65536);
        smem_set = 1;
    }

    // Wh = x @ W_gat^T   [8192 x 48]
    gemm_kernel<<<dim3(1, NN / 64), 256>>>(x, Wg, nullptr, Wh, NN, DH, DIN, 0);
    // s, exp tables, per-tile swizzled bf16-split B (coalesced write-out)
    sab_kernel<<<NN / 256, 256, 65536>>>(avec);
    // tensor-core (HMMA) attention -> g_part  (grid 256, 2 CTAs/SM)
    attn_hmma_kernel<<<NN / 128 * KSPLIT, 256, SM_TOTAL>>>(adj);
    // combine K-splits, normalize, LayerNorm -> g_hn
    reduce_ln_kernel<<<64, 128>>>(gamma, beta);
    // MLP head
    gemm_kernel<<<dim3(DH1 / 64, NN / 64), 256>>>(hn, W1, b1, m1, NN, DH1, DH, 1);
    gemm_kernel<<<dim3(DH2 / 64, NN / 64), 256>>>(m1, W2, b2, m2, NN, DH2, DH1, 1);
    gemm_kernel<<<dim3(1, NN / 64), 256>>>(m2, W3, b3, out, NN, DOUT, DH2, 0);
}